// round 7
// baseline (speedup 1.0000x reference)
#include <cuda_runtime.h>
#include <cuda_bf16.h>

#define IN_DIM   512
#define BATCH    8192
#define GRID_NUM 48
#define NCOEF    (GRID_NUM + 3)   // 51
#define NKNOT    (GRID_NUM + 1)   // 49
#define TILE     64               // dims per block -> 8 dim-tiles
#define THREADS  256              // 64 dims x 4 rows per block iteration
#define NBLOCKS  888              // 148 SMs x 6 blocks: exactly one wave
#define NRG      111              // row-groups per dim-tile (888/8)
#define NRG_TOT  2048             // BATCH/4 row-groups total
#define CELL_LO  24               // x in [0,1) -> t in [24,48)
#define NCELL_S  24

__device__ float4 g_poly[GRID_NUM * IN_DIM];   // [cell][dim] monomial quads
__device__ float  g_lo[IN_DIM];
__device__ float  g_invh[IN_DIM];

#define PREP_DIMS 16
__global__ void prep_kernel(const float* __restrict__ grid,
                            const float* __restrict__ coef) {
    __shared__ float s_c[PREP_DIMS * NCOEF];
    const int tid  = threadIdx.x;
    const int dim0 = blockIdx.x * PREP_DIMS;

    for (int k = tid; k < PREP_DIMS * NCOEF; k += THREADS)
        s_c[k] = coef[dim0 * NCOEF + k];
    if (tid < PREP_DIMS) {
        int i = dim0 + tid;
        float lo = grid[i * NKNOT];
        float hi = grid[i * NKNOT + GRID_NUM];
        g_lo[i]   = lo;
        g_invh[i] = (float)GRID_NUM / (hi - lo);
    }
    __syncthreads();

    for (int k = tid; k < GRID_NUM * PREP_DIMS; k += THREADS) {
        int cell = k >> 4, d = k & (PREP_DIMS - 1);
        const float* c = s_c + d * NCOEF + cell;
        float c0 = c[0], c1 = c[1], c2 = c[2], c3 = c[3];
        float4 a;
        a.x = (c0 + 4.0f * c1 + c2) * (1.0f / 6.0f);
        a.y = (c2 - c0) * 0.5f;
        a.z = (c0 - 2.0f * c1 + c2) * 0.5f;
        a.w = (c3 - c0 + 3.0f * (c1 - c2)) * (1.0f / 6.0f);
        g_poly[cell * IN_DIM + dim0 + d] = a;
    }
}

__global__ __launch_bounds__(THREADS, 6) void bspline_kernel(
    const float* __restrict__ x,
    float* __restrict__ y)
{
    __shared__ float4 s_quad[NCELL_S * TILE];    // 24 KB, conflict-free LDS.128

    const int tid  = threadIdx.x;
    const int bid  = blockIdx.x;                 // 0..887
    const int dim0 = (bid & 7) * TILE;           // 8 dim-tiles
    const int rg0  = bid >> 3;                   // 0..110

    #pragma unroll
    for (int k = tid; k < NCELL_S * TILE; k += THREADS)
        s_quad[k] = g_poly[(CELL_LO + (k >> 6)) * IN_DIM + dim0 + (k & (TILE - 1))];

    const int d    = tid & (TILE - 1);
    const int rofs = tid >> 6;                   // 0..3
    const int col  = dim0 + d;
    const float lo   = g_lo[col];
    const float invh = g_invh[col];

    __syncthreads();

    for (int rg = rg0; rg < NRG_TOT; rg += 4 * NRG) {
        float xv[4], res[4];
        #pragma unroll
        for (int q = 0; q < 4; ++q) {            // MLP=4 streaming loads
            int rr = rg + q * NRG;
            xv[q] = (rr < NRG_TOT) ? x[(rr * 4 + rofs) * IN_DIM + col] : 0.0f;
        }
        #pragma unroll
        for (int q = 0; q < 4; ++q) {
            float t = (xv[q] - lo) * invh;
            int cell = (int)t;
            cell = max(0, min(cell, GRID_NUM - 1));
            float u = t - (float)cell;
            int cs = cell - CELL_LO;
            float4 a;
            if ((unsigned)cs < (unsigned)NCELL_S) {
                a = s_quad[cs * TILE + d];       // hot path: conflict-free LDS.128
            } else {
                a = g_poly[cell * IN_DIM + col]; // never taken for in-range x
            }
            res[q] = fmaf(fmaf(fmaf(a.w, u, a.z), u, a.y), u, a.x);
        }
        #pragma unroll
        for (int q = 0; q < 4; ++q) {
            int rr = rg + q * NRG;
            if (rr < NRG_TOT) y[(rr * 4 + rofs) * IN_DIM + col] = res[q];
        }
    }
}

extern "C" void kernel_launch(void* const* d_in, const int* in_sizes, int n_in,
                              void* d_out, int out_size) {
    const float* x    = (const float*)d_in[0];
    const float* grid = (const float*)d_in[1];
    const float* coef = (const float*)d_in[2];
    float* y = (float*)d_out;

    prep_kernel<<<IN_DIM / PREP_DIMS, THREADS>>>(grid, coef);
    bspline_kernel<<<NBLOCKS, THREADS>>>(x, y);
}

// round 8
// speedup vs baseline: 1.1710x; 1.1710x over previous
#include <cuda_runtime.h>
#include <cuda_bf16.h>

#define IN_DIM   512
#define BATCH    8192
#define GRID_NUM 48
#define NCOEF    (GRID_NUM + 3)   // 51
#define NKNOT    (GRID_NUM + 1)   // 49
#define TILE     64               // dims per block -> 8 dim-tiles
#define THREADS  256
#define NBLOCKS  888              // 148 SMs x 6 blocks: exactly one wave
#define NRG      111              // row-group columns per dim-tile (888/8)
#define NRG_TOT  2048             // BATCH/4
#define CELL_LO  24               // x in [0,1) -> t in [24,48)
#define NCELL_S  24               // staged cells 24..47
#define NCOL_S   27               // coef columns needed: 24..50

__global__ __launch_bounds__(THREADS, 6) void bspline_fused_kernel(
    const float* __restrict__ x,
    const float* __restrict__ grid,
    const float* __restrict__ coef,
    float* __restrict__ y)
{
    __shared__ float4 s_quad[NCELL_S * TILE];   // 24.0 KB, [cell-24][d]
    __shared__ float  s_c[TILE * NCOL_S];       //  6.9 KB, [d][c-24]

    const int tid  = threadIdx.x;
    const int bid  = blockIdx.x;
    const int dim0 = (bid & 7) * TILE;
    const int rg0  = bid >> 3;                  // 0..110

    // Stage coef columns 24..50 for this block's 64 dims (contiguous 27-float runs).
    #pragma unroll
    for (int k = tid; k < TILE * NCOL_S; k += THREADS) {
        int d = k / NCOL_S, c = k - d * NCOL_S;
        s_c[k] = coef[(dim0 + d) * NCOEF + CELL_LO + c];
    }
    __syncthreads();

    // Build monomial quad table: 6 quads/thread. s_c stride 27 -> conflict-free LDS;
    // s_quad STS.128 banks 4d mod 32 -> conflict-free.
    #pragma unroll
    for (int k = tid; k < NCELL_S * TILE; k += THREADS) {
        int cell = k >> 6, d = k & (TILE - 1);
        const float* c = s_c + d * NCOL_S + cell;
        float c0 = c[0], c1 = c[1], c2 = c[2], c3 = c[3];
        float4 a;
        a.x = (c0 + 4.0f * c1 + c2) * (1.0f / 6.0f);
        a.y = (c2 - c0) * 0.5f;
        a.z = (c0 - 2.0f * c1 + c2) * 0.5f;
        a.w = (c3 - c0 + 3.0f * (c1 - c2)) * (1.0f / 6.0f);
        s_quad[k] = a;
    }

    const int d    = tid & (TILE - 1);
    const int rofs = tid >> 6;                  // 0..3
    const int col  = dim0 + d;
    const float glo  = grid[col * NKNOT];
    const float ghi  = grid[col * NKNOT + GRID_NUM];
    const float invh = (float)GRID_NUM / (ghi - glo);

    __syncthreads();

    const int idx0    = (rg0 * 4 + rofs) * IN_DIM + col;
    const int max_idx = ((NRG_TOT - 1) * 4 + rofs) * IN_DIM + col;
    const int Q_OFF   = NRG * 4 * IN_DIM;       // 227328: offset per q-slot
    const int IT_OFF  = 4 * Q_OFF;              // offset per outer iteration

    #pragma unroll
    for (int it = 0; it < 5; ++it) {
        const int base = idx0 + it * IT_OFF;
        float xv[4], res[4];
        #pragma unroll
        for (int q = 0; q < 4; ++q) {           // MLP=4 streaming loads
            int idx = base + q * Q_OFF;
            if (it == 4) idx = min(idx, max_idx);   // tail clamp: duplicate rows, identical values
            xv[q] = x[idx];
        }
        #pragma unroll
        for (int q = 0; q < 4; ++q) {
            float t = (xv[q] - glo) * invh;
            int cell = (int)t;
            cell = max(0, min(cell, GRID_NUM - 1));
            float u = t - (float)cell;
            int cs = cell - CELL_LO;
            float4 a;
            if ((unsigned)cs < (unsigned)NCELL_S) {
                a = s_quad[cs * TILE + d];      // hot path: conflict-free LDS.128
            } else {                            // never taken for in-range x; correct anyway
                const float* c = coef + col * NCOEF + cell;
                float c0 = c[0], c1 = c[1], c2 = c[2], c3 = c[3];
                a.x = (c0 + 4.0f * c1 + c2) * (1.0f / 6.0f);
                a.y = (c2 - c0) * 0.5f;
                a.z = (c0 - 2.0f * c1 + c2) * 0.5f;
                a.w = (c3 - c0 + 3.0f * (c1 - c2)) * (1.0f / 6.0f);
            }
            res[q] = fmaf(fmaf(fmaf(a.w, u, a.z), u, a.y), u, a.x);
        }
        #pragma unroll
        for (int q = 0; q < 4; ++q) {
            int idx = base + q * Q_OFF;
            if (it == 4) idx = min(idx, max_idx);
            y[idx] = res[q];
        }
    }
}

extern "C" void kernel_launch(void* const* d_in, const int* in_sizes, int n_in,
                              void* d_out, int out_size) {
    const float* x    = (const float*)d_in[0];
    const float* grid = (const float*)d_in[1];
    const float* coef = (const float*)d_in[2];
    float* y = (float*)d_out;

    bspline_fused_kernel<<<NBLOCKS, THREADS>>>(x, grid, coef, y);
}